// round 3
// baseline (speedup 1.0000x reference)
#include <cuda_runtime.h>
#include <math.h>

typedef unsigned long long ull;

// ---------------------------------------------------------------------------
// MetaCNNLSTM: conv1d(64->256,k9,pad4) -> GN(8)+ReLU -> 3x LSTM(512) -> mean
// pool -> linear head.  B=32, T=512, fp32 everywhere (f32x2-packed math).
// ---------------------------------------------------------------------------
#define BB   32
#define CIN  64
#define TT   512
#define FF   256
#define KK   9
#define GG   8
#define HH   512
#define G4   2048
#define NCLS 50
#define RNB  128    // persistent blocks in recurrence (must be co-resident)

// ------------------------- scratch (static device globals) -----------------
__device__ float   g_conv[BB * FF * TT];     // conv out (B,F,T)
__device__ float   g_xt[BB * TT * FF];       // GN+ReLU, (B*T, F)
__device__ float   g_xp[BB * TT * G4];       // input projections (B*T, 4H)
__device__ float   g_h1[BB * TT * HH];       // layer-1 output
__device__ float   g_h2[BB * TT * HH];       // layer-2 output
__device__ float   g_htb[2][HH * BB];        // h ping-pong, [unit][batch]
__device__ float   g_feat[BB * HH];          // pooled features
__device__ float2  g_stat[BB * GG];          // GN (mean, rstd)
__device__ unsigned g_cnt;                   // global barrier count
__device__ unsigned g_gen;                   // global barrier generation

// ------------------------- f32x2 helpers ------------------------------------
__device__ __forceinline__ void fma2(ull& d, ull a, ull b) {
    asm("fma.rn.f32x2 %0, %1, %2, %0;" : "+l"(d) : "l"(a), "l"(b));
}
__device__ __forceinline__ ull add2(ull a, ull b) {
    ull r; asm("add.rn.f32x2 %0, %1, %2;" : "=l"(r) : "l"(a), "l"(b)); return r;
}
__device__ __forceinline__ ull pk2(float x) {
    ull r; asm("mov.b64 %0, {%1, %1};" : "=l"(r) : "f"(x)); return r;
}
union UF2 { ull u; float2 f; };

// ------------------------------- conv1d ------------------------------------
// grid (T/128, B), 256 threads. dyn smem: xs[64][136] + ws[8][64][9]
#define CONV_SMEM ((64 * 136 + 8 * 64 * 9) * 4)
__global__ __launch_bounds__(256) void conv_kernel(
    const float* __restrict__ x, const float* __restrict__ w)
{
    extern __shared__ float sm[];
    float* xs = sm;              // [64][136]
    float* ws = sm + 64 * 136;   // [8][64][9]
    const int b   = blockIdx.y;
    const int t0  = blockIdx.x * 128;
    const int tid = threadIdx.x;

    for (int i = tid; i < 64 * 136; i += 256) {
        int c = i / 136, j = i - c * 136;
        int t = t0 - 4 + j;
        xs[i] = (t >= 0 && t < TT) ? x[(b * CIN + c) * TT + t] : 0.f;
    }
    const int lane = tid & 31;
    const int wf   = tid >> 5;      // local filter 0..7
    const int tl   = lane * 4;      // local t 0..124

    for (int fc = 0; fc < FF; fc += 8) {
        __syncthreads();
        for (int i = tid; i < 8 * 64 * 9; i += 256)
            ws[i] = w[fc * 64 * 9 + i];
        __syncthreads();
        const int f = fc + wf;
        float a0 = 0.f, a1 = 0.f, a2 = 0.f, a3 = 0.f;
        for (int c = 0; c < 64; ++c) {
            const float* xr = &xs[c * 136 + tl];
            const float* wr = &ws[(wf * 64 + c) * 9];
            float4 p0 = *(const float4*)(xr);
            float4 p1 = *(const float4*)(xr + 4);
            float4 p2 = *(const float4*)(xr + 8);
            float xv[12] = {p0.x, p0.y, p0.z, p0.w, p1.x, p1.y, p1.z, p1.w,
                            p2.x, p2.y, p2.z, p2.w};
#pragma unroll
            for (int k = 0; k < 9; ++k) {
                float wk = wr[k];
                a0 += wk * xv[k];
                a1 += wk * xv[k + 1];
                a2 += wk * xv[k + 2];
                a3 += wk * xv[k + 3];
            }
        }
        *(float4*)&g_conv[(b * FF + f) * TT + t0 + tl] =
            make_float4(a0, a1, a2, a3);
    }
}

// ------------------------------ groupnorm stats ------------------------------
__global__ __launch_bounds__(256) void gn_stats_kernel()
{
    const int b = blockIdx.x >> 3, g = blockIdx.x & 7;
    __shared__ float ssum[256], ssq[256];
    const int tid = threadIdx.x;
    const float* base = g_conv + (b * FF + g * 32) * TT;
    float s = 0.f, q = 0.f;
    for (int i = tid; i < 32 * TT; i += 256) {
        float v = base[i];
        s += v; q += v * v;
    }
    ssum[tid] = s; ssq[tid] = q;
    __syncthreads();
    for (int o = 128; o > 0; o >>= 1) {
        if (tid < o) { ssum[tid] += ssum[tid + o]; ssq[tid] += ssq[tid + o]; }
        __syncthreads();
    }
    if (tid == 0) {
        float mean = ssum[0] * (1.f / 16384.f);
        float var  = ssq[0] * (1.f / 16384.f) - mean * mean;
        g_stat[b * GG + g] = make_float2(mean, rsqrtf(var + 1e-5f));
    }
}

// -------- GN apply + ReLU + transpose (B,F,T) -> (B*T, F) -------------------
// grid (T/32, F/32, B), 256 threads
__global__ __launch_bounds__(256) void gn_apply_kernel(
    const float* __restrict__ gamma, const float* __restrict__ beta)
{
    __shared__ float tile[32][33];
    const int b  = blockIdx.z;
    const int f0 = blockIdx.y * 32;
    const int t0 = blockIdx.x * 32;
    const int tx = threadIdx.x & 31, ty = threadIdx.x >> 5;   // ty 0..7
#pragma unroll
    for (int j = 0; j < 4; ++j) {
        int f = f0 + ty + j * 8;
        float2 st = g_stat[b * GG + (f >> 5)];
        float v = g_conv[(b * FF + f) * TT + t0 + tx];
        v = (v - st.x) * st.y * gamma[f] + beta[f];
        tile[ty + j * 8][tx] = fmaxf(v, 0.f);
    }
    __syncthreads();
#pragma unroll
    for (int j = 0; j < 4; ++j) {
        int t = t0 + ty + j * 8;
        g_xt[(b * TT + t) * FF + f0 + tx] = tile[tx][ty + j * 8];
    }
}

// --------------------- projection GEMM: C = A @ B^T + bias ------------------
// A: (M, Ka) row-major. Bm: (2048, Ka) row-major. C: (M, 2048).
// grid (N/64=32, M/128), 256 threads, 128x64 tile, 8x4 per thread, f32x2.
__global__ __launch_bounds__(256) void gemm_kernel(
    const float* __restrict__ A, const float* __restrict__ Bm,
    const float* __restrict__ bias, float* __restrict__ C, int Ka)
{
    __shared__ float As[8][132];
    __shared__ float Bs[8][68];
    const int bm = blockIdx.y * 128, bn = blockIdx.x * 64;
    const int tid = threadIdx.x;
    const int arow = tid >> 1;                 // 0..127
    const int ak4  = (tid & 1) * 4;            // 0 or 4
    const int brow = (tid & 127) >> 1;         // 0..63
    const bool bact = tid < 128;
    const int tm = (tid & 15) * 8;             // 8 m-rows
    const int tn = (tid >> 4) * 4;             // 4 n-cols

    ull acc[4][4];
#pragma unroll
    for (int i = 0; i < 4; ++i)
#pragma unroll
        for (int j = 0; j < 4; ++j) acc[i][j] = 0ull;

    for (int ko = 0; ko < Ka; ko += 8) {
        float4 av = *(const float4*)&A[(bm + arow) * Ka + ko + ak4];
        float4 bv = make_float4(0.f, 0.f, 0.f, 0.f);
        if (bact) bv = *(const float4*)&Bm[(bn + brow) * Ka + ko + ak4];
        __syncthreads();
        As[ak4 + 0][arow] = av.x; As[ak4 + 1][arow] = av.y;
        As[ak4 + 2][arow] = av.z; As[ak4 + 3][arow] = av.w;
        if (bact) {
            Bs[ak4 + 0][brow] = bv.x; Bs[ak4 + 1][brow] = bv.y;
            Bs[ak4 + 2][brow] = bv.z; Bs[ak4 + 3][brow] = bv.w;
        }
        __syncthreads();
#pragma unroll
        for (int k = 0; k < 8; ++k) {
            const ulonglong2* ap = (const ulonglong2*)&As[k][tm];
            ulonglong2 a01 = ap[0];   // m-pairs (tm,tm+1),(tm+2,tm+3)
            ulonglong2 a23 = ap[1];   // m-pairs (tm+4,tm+5),(tm+6,tm+7)
            float4 b4 = *(const float4*)&Bs[k][tn];
            ull b0 = pk2(b4.x), b1 = pk2(b4.y), b2 = pk2(b4.z), b3 = pk2(b4.w);
            fma2(acc[0][0], a01.x, b0); fma2(acc[0][1], a01.x, b1);
            fma2(acc[0][2], a01.x, b2); fma2(acc[0][3], a01.x, b3);
            fma2(acc[1][0], a01.y, b0); fma2(acc[1][1], a01.y, b1);
            fma2(acc[1][2], a01.y, b2); fma2(acc[1][3], a01.y, b3);
            fma2(acc[2][0], a23.x, b0); fma2(acc[2][1], a23.x, b1);
            fma2(acc[2][2], a23.x, b2); fma2(acc[2][3], a23.x, b3);
            fma2(acc[3][0], a23.y, b0); fma2(acc[3][1], a23.y, b1);
            fma2(acc[3][2], a23.y, b2); fma2(acc[3][3], a23.y, b3);
        }
    }
    float4 bb = *(const float4*)&bias[bn + tn];
#pragma unroll
    for (int mp = 0; mp < 4; ++mp) {
        UF2 u0, u1, u2, u3;
        u0.u = acc[mp][0]; u1.u = acc[mp][1];
        u2.u = acc[mp][2]; u3.u = acc[mp][3];
        int row = bm + tm + 2 * mp;
        *(float4*)&C[row * G4 + bn + tn] =
            make_float4(u0.f.x + bb.x, u1.f.x + bb.y, u2.f.x + bb.z, u3.f.x + bb.w);
        *(float4*)&C[(row + 1) * G4 + bn + tn] =
            make_float4(u0.f.y + bb.x, u1.f.y + bb.y, u2.f.y + bb.z, u3.f.y + bb.w);
    }
}

// ----------------------- zero ping-pong h buffer ---------------------------
__global__ void zero_h_kernel()
{
    int i = blockIdx.x * 256 + threadIdx.x;   // grid 64 -> 16384
    __stcg(&g_htb[0][i], 0.f);
}

// ------------------------- persistent recurrence ---------------------------
__device__ __forceinline__ void grid_bar()
{
    __syncthreads();
    if (threadIdx.x == 0) {
        unsigned gen = *(volatile unsigned*)&g_gen;
        __threadfence();
        if (atomicAdd(&g_cnt, 1u) == RNB - 1) {
            g_cnt = 0;
            __threadfence();
            atomicAdd(&g_gen, 1u);
        } else {
            while (*(volatile unsigned*)&g_gen == gen) __nanosleep(40);
        }
    }
    __syncthreads();
}

// inner f32x2 GEMM on one 128-row chunk of h
__device__ __forceinline__ void rcomp(ull* acc, const float* wr8,
                                      const float* buf, int s)
{
#pragma unroll
    for (int j = 0; j < 8; ++j) {
        ull wv = pk2(wr8[j]);
        const ulonglong2* hp = (const ulonglong2*)(buf + (s * 8 + j) * 32);
#pragma unroll
        for (int q = 0; q < 8; ++q) {
            ulonglong2 hv = hp[q];
            fma2(acc[2 * q],     wv, hv.x);
            fma2(acc[2 * q + 1], wv, hv.y);
        }
    }
}

// smem: hb0[4096] + hb1[4096] + part[8*16][34]
#define REC_SMEM ((8192 + 8 * 16 * 34) * 4)
__global__ __launch_bounds__(256) void rec_kernel(
    const float* __restrict__ w_hh, const float* __restrict__ xp,
    float* __restrict__ out, int do_pool)
{
    extern __shared__ float sm[];
    float* hb0  = sm;
    float* hb1  = sm + 4096;
    float* part = sm + 8192;
    const int tid  = threadIdx.x;
    const int lane = tid & 31;
    const int w    = tid >> 5;
    const int s    = tid >> 4;      // k-slice 0..15
    const int r    = tid & 15;      // gate-row 0..15
    const int gate = r >> 2;
    const int u    = r & 3;
    const int ug   = blockIdx.x * 4 + u;

    // W_hh slice -> registers (fixed for whole layer): 32 k per thread, 4 chunks
    float wreg[32];
    {
        const float* wp = w_hh + (gate * HH + ug) * HH;
#pragma unroll
        for (int c = 0; c < 4; ++c) {
            float4 v0 = *(const float4*)(wp + c * 128 + s * 8);
            float4 v1 = *(const float4*)(wp + c * 128 + s * 8 + 4);
            wreg[c * 8 + 0] = v0.x; wreg[c * 8 + 1] = v0.y;
            wreg[c * 8 + 2] = v0.z; wreg[c * 8 + 3] = v0.w;
            wreg[c * 8 + 4] = v1.x; wreg[c * 8 + 5] = v1.y;
            wreg[c * 8 + 6] = v1.z; wreg[c * 8 + 7] = v1.w;
        }
    }
    // cell-thread mapping (tid < 128): (unit cu, batch cb)
    const int cu  = tid >> 5;
    const int cb  = tid & 31;
    const int cug = blockIdx.x * 4 + cu;
    float c_state = 0.f, hsum = 0.f;

    for (int t = 0; t < TT; ++t) {
        const int p = t & 1;
        const float4* src = (const float4*)(g_htb[p]);
        float4 sa[4], sb[4];
#pragma unroll
        for (int i = 0; i < 4; ++i) sa[i] = __ldcg(src + tid + i * 256);
#pragma unroll
        for (int i = 0; i < 4; ++i) sb[i] = __ldcg(src + 1024 + tid + i * 256);
        float xg0 = 0.f, xg1 = 0.f, xg2 = 0.f, xg3 = 0.f;
        if (tid < 128) {
            const float* xpp = xp + (cb * TT + t) * G4 + cug;
            xg0 = __ldg(xpp);
            xg1 = __ldg(xpp + HH);
            xg2 = __ldg(xpp + 2 * HH);
            xg3 = __ldg(xpp + 3 * HH);
        }
#pragma unroll
        for (int i = 0; i < 4; ++i) ((float4*)hb0)[tid + i * 256] = sa[i];
        __syncthreads();

        ull acc[16];
#pragma unroll
        for (int i = 0; i < 16; ++i) acc[i] = 0ull;

        // chunk 0: stage c1, prefetch c2
#pragma unroll
        for (int i = 0; i < 4; ++i) ((float4*)hb1)[tid + i * 256] = sb[i];
#pragma unroll
        for (int i = 0; i < 4; ++i) sa[i] = __ldcg(src + 2048 + tid + i * 256);
        rcomp(acc, wreg + 0, hb0, s);
        __syncthreads();
        // chunk 1: stage c2, prefetch c3
#pragma unroll
        for (int i = 0; i < 4; ++i) ((float4*)hb0)[tid + i * 256] = sa[i];
#pragma unroll
        for (int i = 0; i < 4; ++i) sb[i] = __ldcg(src + 3072 + tid + i * 256);
        rcomp(acc, wreg + 8, hb1, s);
        __syncthreads();
        // chunk 2: stage c3
#pragma unroll
        for (int i = 0; i < 4; ++i) ((float4*)hb1)[tid + i * 256] = sb[i];
        rcomp(acc, wreg + 16, hb0, s);
        __syncthreads();
        // chunk 3
        rcomp(acc, wreg + 24, hb1, s);

        // reduce slot pairs (s, s^1) within warp via shfl
#pragma unroll
        for (int i = 0; i < 16; ++i) {
            ull o = __shfl_xor_sync(0xffffffffu, acc[i], 16);
            acc[i] = add2(acc[i], o);
        }
        {
            const int io = (lane >> 4) * 8;       // both halves write half
            ull* pr = (ull*)(part + (w * 16 + r) * 34);
#pragma unroll
            for (int i = 0; i < 8; ++i) pr[io + i] = acc[io + i];
        }
        __syncthreads();

        if (tid < 128) {
            float g0 = xg0, g1 = xg1, g2 = xg2, g3 = xg3;
#pragma unroll
            for (int w8 = 0; w8 < 8; ++w8) {
                const float* pb = part + (w8 * 16) * 34 + cb;
                g0 += pb[(cu)      * 34];
                g1 += pb[(4 + cu)  * 34];
                g2 += pb[(8 + cu)  * 34];
                g3 += pb[(12 + cu) * 34];
            }
            float ig  = 1.f / (1.f + __expf(-g0));
            float fg  = 1.f / (1.f + __expf(-g1));
            float gg_ = tanhf(g2);
            float og  = 1.f / (1.f + __expf(-g3));
            c_state = fg * c_state + ig * gg_;
            float hv = og * tanhf(c_state);
            __stcg(&g_htb[p ^ 1][cug * 32 + cb], hv);
            if (out) out[(cb * TT + t) * HH + cug] = hv;
            hsum += hv;
        }
        grid_bar();
    }
    if (do_pool && tid < 128)
        g_feat[cb * HH + cug] = hsum * (1.f / 512.f);
}

// --------------------------------- head ------------------------------------
// grid (NCLS, B), 64 threads
__global__ __launch_bounds__(64) void head_kernel(
    const float* __restrict__ hw, const float* __restrict__ hb,
    float* __restrict__ outp)
{
    const int c = blockIdx.x, b = blockIdx.y;
    float s = 0.f;
    for (int k = threadIdx.x; k < HH; k += 64)
        s += g_feat[b * HH + k] * hw[c * HH + k];
    __shared__ float red[2];
#pragma unroll
    for (int o = 16; o; o >>= 1) s += __shfl_down_sync(0xffffffffu, s, o);
    if ((threadIdx.x & 31) == 0) red[threadIdx.x >> 5] = s;
    __syncthreads();
    if (threadIdx.x == 0) outp[b * NCLS + c] = red[0] + red[1] + hb[c];
}

// ------------------------------ launcher -----------------------------------
extern "C" void kernel_launch(void* const* d_in, const int* in_sizes, int n_in,
                              void* d_out, int out_size)
{
    const float* x_emg  = (const float*)d_in[0];
    const float* conv_w = (const float*)d_in[1];
    const float* gamma  = (const float*)d_in[2];
    const float* beta   = (const float*)d_in[3];
    const float *w_ih[3], *w_hh[3], *bi[3], *head_w, *head_b;

    if (in_sizes[4] == 4 * HH * FF) {          // signature order
        for (int l = 0; l < 3; ++l) {
            w_ih[l] = (const float*)d_in[4 + 3 * l];
            w_hh[l] = (const float*)d_in[5 + 3 * l];
            bi[l]   = (const float*)d_in[6 + 3 * l];
        }
        head_w = (const float*)d_in[13];
        head_b = (const float*)d_in[14];
    } else {                                    // dict order
        head_w = (const float*)d_in[4];
        head_b = (const float*)d_in[5];
        for (int l = 0; l < 3; ++l) {
            w_ih[l] = (const float*)d_in[6 + 3 * l];
            w_hh[l] = (const float*)d_in[7 + 3 * l];
            bi[l]   = (const float*)d_in[8 + 3 * l];
        }
    }
    float* out = (float*)d_out;

    cudaFuncSetAttribute(conv_kernel,
        cudaFuncAttributeMaxDynamicSharedMemorySize, CONV_SMEM);
    cudaFuncSetAttribute(rec_kernel,
        cudaFuncAttributeMaxDynamicSharedMemorySize, REC_SMEM);

    float* g_xp_p;   cudaGetSymbolAddress((void**)&g_xp_p, g_xp);
    float* g_xt_p;   cudaGetSymbolAddress((void**)&g_xt_p, g_xt);
    float* g_h1_p;   cudaGetSymbolAddress((void**)&g_h1_p, g_h1);
    float* g_h2_p;   cudaGetSymbolAddress((void**)&g_h2_p, g_h2);

    // conv + groupnorm + relu + transpose
    conv_kernel<<<dim3(TT / 128, BB), 256, CONV_SMEM>>>(x_emg, conv_w);
    gn_stats_kernel<<<BB * GG, 256>>>();
    gn_apply_kernel<<<dim3(TT / 32, FF / 32, BB), 256>>>(gamma, beta);

    const float* lay_in[3]  = {g_xt_p, g_h1_p, g_h2_p};
    float*       lay_out[3] = {g_h1_p, g_h2_p, nullptr};
    const int    lay_ka[3]  = {FF, HH, HH};

    for (int l = 0; l < 3; ++l) {
        gemm_kernel<<<dim3(G4 / 64, BB * TT / 128), 256>>>(
            lay_in[l], w_ih[l], bi[l], g_xp_p, lay_ka[l]);
        zero_h_kernel<<<64, 256>>>();
        rec_kernel<<<RNB, 256, REC_SMEM>>>(w_hh[l], g_xp_p, lay_out[l],
                                           l == 2 ? 1 : 0);
    }
    head_kernel<<<dim3(NCLS, BB), 64>>>(head_w, head_b, out);
}

// round 4
// speedup vs baseline: 1.1290x; 1.1290x over previous
#include <cuda_runtime.h>
#include <math.h>

typedef unsigned long long ull;

// ---------------------------------------------------------------------------
// MetaCNNLSTM: conv1d(64->256,k9,pad4) -> GN(8)+ReLU -> 3x LSTM(512) -> mean
// pool -> linear head.  B=32, T=512, fp32.
// Wavefront-fused recurrence: one persistent kernel runs all 3 LSTM layers,
// slot s computes (L1 t=s, L2 t=s-1, L3 t=s-2). 514 grid barriers total.
// ---------------------------------------------------------------------------
#define BB   32
#define CIN  64
#define TT   512
#define FF   256
#define GG   8
#define HH   512
#define G4   2048
#define NCLS 50
#define RNB  128    // persistent blocks (must be co-resident; <= 152 SMs)
#define NSLOT (TT + 2)

// ------------------------- scratch (static device globals) -----------------
__device__ float   g_conv[BB * FF * TT];     // conv out (B,F,T)
__device__ float   g_xt[BB * TT * FF];       // GN+ReLU, (B*T, F)
__device__ float   g_xp[BB * TT * G4];       // layer-1 input projections
__device__ float   g_hb1[2][HH * BB];        // h1 ping-pong [unit][batch]
__device__ float   g_hb2[2][HH * BB];        // h2 ping-pong
__device__ float   g_hb3[2][HH * BB];        // h3 ping-pong
__device__ float   g_feat[BB * HH];          // pooled features
__device__ float2  g_stat[BB * GG];          // GN (mean, rstd)
__device__ unsigned g_cnt;                   // global barrier count
__device__ unsigned g_gen;                   // global barrier generation

// ------------------------- f32x2 / async helpers ----------------------------
__device__ __forceinline__ void fma2(ull& d, ull a, ull b) {
    asm("fma.rn.f32x2 %0, %1, %2, %0;" : "+l"(d) : "l"(a), "l"(b));
}
__device__ __forceinline__ ull pk2(float x) {
    ull r; asm("mov.b64 %0, {%1, %1};" : "=l"(r) : "f"(x)); return r;
}
#define CP_ASYNC16(dst_u32, src_ptr) \
    asm volatile("cp.async.cg.shared.global [%0], [%1], 16;" \
                 :: "r"(dst_u32), "l"(src_ptr))
#define CP_COMMIT() asm volatile("cp.async.commit_group;")
#define CP_WAIT(n)  asm volatile("cp.async.wait_group " #n ";" ::: "memory")

// ------------------------------- conv1d ------------------------------------
#define CONV_SMEM ((64 * 136 + 8 * 64 * 9) * 4)
__global__ __launch_bounds__(256) void conv_kernel(
    const float* __restrict__ x, const float* __restrict__ w)
{
    extern __shared__ float sm[];
    float* xs = sm;              // [64][136]
    float* ws = sm + 64 * 136;   // [8][64][9]
    const int b   = blockIdx.y;
    const int t0  = blockIdx.x * 128;
    const int tid = threadIdx.x;

    for (int i = tid; i < 64 * 136; i += 256) {
        int c = i / 136, j = i - c * 136;
        int t = t0 - 4 + j;
        xs[i] = (t >= 0 && t < TT) ? x[(b * CIN + c) * TT + t] : 0.f;
    }
    const int lane = tid & 31;
    const int wf   = tid >> 5;
    const int tl   = lane * 4;

    for (int fc = 0; fc < FF; fc += 8) {
        __syncthreads();
        for (int i = tid; i < 8 * 64 * 9; i += 256)
            ws[i] = w[fc * 64 * 9 + i];
        __syncthreads();
        const int f = fc + wf;
        float a0 = 0.f, a1 = 0.f, a2 = 0.f, a3 = 0.f;
        for (int c = 0; c < 64; ++c) {
            const float* xr = &xs[c * 136 + tl];
            const float* wr = &ws[(wf * 64 + c) * 9];
            float4 p0 = *(const float4*)(xr);
            float4 p1 = *(const float4*)(xr + 4);
            float4 p2 = *(const float4*)(xr + 8);
            float xv[12] = {p0.x, p0.y, p0.z, p0.w, p1.x, p1.y, p1.z, p1.w,
                            p2.x, p2.y, p2.z, p2.w};
#pragma unroll
            for (int k = 0; k < 9; ++k) {
                float wk = wr[k];
                a0 += wk * xv[k];
                a1 += wk * xv[k + 1];
                a2 += wk * xv[k + 2];
                a3 += wk * xv[k + 3];
            }
        }
        *(float4*)&g_conv[(b * FF + f) * TT + t0 + tl] =
            make_float4(a0, a1, a2, a3);
    }
}

// ------------------------------ groupnorm stats -----------------------------
__global__ __launch_bounds__(256) void gn_stats_kernel()
{
    const int b = blockIdx.x >> 3, g = blockIdx.x & 7;
    __shared__ float ssum[256], ssq[256];
    const int tid = threadIdx.x;
    const float* base = g_conv + (b * FF + g * 32) * TT;
    float s = 0.f, q = 0.f;
    for (int i = tid; i < 32 * TT; i += 256) {
        float v = base[i];
        s += v; q += v * v;
    }
    ssum[tid] = s; ssq[tid] = q;
    __syncthreads();
    for (int o = 128; o > 0; o >>= 1) {
        if (tid < o) { ssum[tid] += ssum[tid + o]; ssq[tid] += ssq[tid + o]; }
        __syncthreads();
    }
    if (tid == 0) {
        float mean = ssum[0] * (1.f / 16384.f);
        float var  = ssq[0] * (1.f / 16384.f) - mean * mean;
        g_stat[b * GG + g] = make_float2(mean, rsqrtf(var + 1e-5f));
    }
}

// -------- GN apply + ReLU + transpose (B,F,T) -> (B*T, F) -------------------
__global__ __launch_bounds__(256) void gn_apply_kernel(
    const float* __restrict__ gamma, const float* __restrict__ beta)
{
    __shared__ float tile[32][33];
    const int b  = blockIdx.z;
    const int f0 = blockIdx.y * 32;
    const int t0 = blockIdx.x * 32;
    const int tx = threadIdx.x & 31, ty = threadIdx.x >> 5;
#pragma unroll
    for (int j = 0; j < 4; ++j) {
        int f = f0 + ty + j * 8;
        float2 st = g_stat[b * GG + (f >> 5)];
        float v = g_conv[(b * FF + f) * TT + t0 + tx];
        v = (v - st.x) * st.y * gamma[f] + beta[f];
        tile[ty + j * 8][tx] = fmaxf(v, 0.f);
    }
    __syncthreads();
#pragma unroll
    for (int j = 0; j < 4; ++j) {
        int t = t0 + ty + j * 8;
        g_xt[(b * TT + t) * FF + f0 + tx] = tile[tx][ty + j * 8];
    }
}

// --------------------- projection GEMM: C = A @ B^T + bias ------------------
// (layer-1 only now).  64x64 tile, 4x4 per thread (R2 version, known-good).
__global__ __launch_bounds__(256) void gemm_kernel(
    const float* __restrict__ A, const float* __restrict__ Bm,
    const float* __restrict__ bias, float* __restrict__ C, int Ka)
{
    __shared__ float As[16][64];
    __shared__ float Bs[16][64];
    const int bm = blockIdx.y * 64, bn = blockIdx.x * 64;
    const int tid = threadIdx.x;
    const int lm  = tid >> 2;
    const int lk4 = (tid & 3) * 4;
    const int tm  = (tid & 15) * 4;
    const int tn  = (tid >> 4) * 4;

    float acc[4][4];
#pragma unroll
    for (int i = 0; i < 4; ++i)
#pragma unroll
        for (int j = 0; j < 4; ++j) acc[i][j] = 0.f;

    for (int ko = 0; ko < Ka; ko += 16) {
        float4 av = *(const float4*)&A[(bm + lm) * Ka + ko + lk4];
        float4 bv = *(const float4*)&Bm[(bn + lm) * Ka + ko + lk4];
        __syncthreads();
        As[lk4 + 0][lm] = av.x; As[lk4 + 1][lm] = av.y;
        As[lk4 + 2][lm] = av.z; As[lk4 + 3][lm] = av.w;
        Bs[lk4 + 0][lm] = bv.x; Bs[lk4 + 1][lm] = bv.y;
        Bs[lk4 + 2][lm] = bv.z; Bs[lk4 + 3][lm] = bv.w;
        __syncthreads();
#pragma unroll
        for (int k = 0; k < 16; ++k) {
            float4 a4 = *(const float4*)&As[k][tm];
            float4 b4 = *(const float4*)&Bs[k][tn];
            float am[4] = {a4.x, a4.y, a4.z, a4.w};
            float bn4[4] = {b4.x, b4.y, b4.z, b4.w};
#pragma unroll
            for (int i = 0; i < 4; ++i)
#pragma unroll
                for (int j = 0; j < 4; ++j) acc[i][j] += am[i] * bn4[j];
        }
    }
#pragma unroll
    for (int i = 0; i < 4; ++i) {
        int row = bm + tm + i;
#pragma unroll
        for (int j = 0; j < 4; ++j)
            C[row * G4 + bn + tn + j] = acc[i][j] + bias[bn + tn + j];
    }
}

// ----------------------- zero ping-pong h buffers ---------------------------
__global__ void zero_h_kernel()
{
    int i = blockIdx.x * 256 + threadIdx.x;   // grid 128 -> 32768
    ((float*)g_hb1)[i] = 0.f;
    ((float*)g_hb2)[i] = 0.f;
    ((float*)g_hb3)[i] = 0.f;
}

// ------------------------- grid barrier -------------------------------------
__device__ __forceinline__ void grid_bar()
{
    __syncthreads();
    if (threadIdx.x == 0) {
        unsigned gen = *(volatile unsigned*)&g_gen;
        __threadfence();
        if (atomicAdd(&g_cnt, 1u) == RNB - 1) {
            g_cnt = 0;
            __threadfence();
            atomicAdd(&g_gen, 1u);
        } else {
            while (*(volatile unsigned*)&g_gen == gen) __nanosleep(32);
        }
    }
    __syncthreads();
}

// -------------------- per-thread GEMM slice (f32x2) -------------------------
// acc[i] accumulates batch pair (2i, 2i+1) for this thread's row & k-slice.
__device__ __forceinline__ void gslice(ull* acc, const float* __restrict__ w,
                                       const float* hbase, int nk4)
{
#pragma unroll
    for (int i = 0; i < 16; ++i) acc[i] = 0ull;
#pragma unroll 4
    for (int k4 = 0; k4 < nk4; ++k4) {
        float4 w4 = __ldg((const float4*)(w + k4 * 4));
        float wa[4] = {w4.x, w4.y, w4.z, w4.w};
#pragma unroll
        for (int j = 0; j < 4; ++j) {
            ull wv = pk2(wa[j]);
            const ulonglong2* hp =
                (const ulonglong2*)(hbase + (k4 * 4 + j) * 32);
#pragma unroll
            for (int q = 0; q < 8; ++q) {
                ulonglong2 hv = hp[q];
                fma2(acc[2 * q],     wv, hv.x);
                fma2(acc[2 * q + 1], wv, hv.y);
            }
        }
    }
}

// ------------------- fused 3-layer wavefront recurrence ---------------------
// smem: buf1/2/3: [512 units][32 batch] staged h vectors (64KB each)
//       part: [16 slice][16 row][34]  (34KB)
#define FSMEM ((3 * HH * BB + 16 * 16 * 34) * 4)
__global__ __launch_bounds__(256) void fused_rec_kernel(
    const float* __restrict__ xp,
    const float* __restrict__ whh1,
    const float* __restrict__ wih2, const float* __restrict__ whh2,
    const float* __restrict__ b2,
    const float* __restrict__ wih3, const float* __restrict__ whh3,
    const float* __restrict__ b3)
{
    extern __shared__ float sm[];
    float* buf1 = sm;                  // h1[s-1]
    float* buf2 = sm + HH * BB;        // h2[s-2]
    float* buf3 = sm + 2 * HH * BB;    // h3[s-3]
    float* part = sm + 3 * HH * BB;    // [16][16][34]

    const int tid = threadIdx.x;
    const int r   = tid & 15;          // gemm row 0..15 (= gate*4 + unit)
    const int s16 = tid >> 4;          // k-slice 0..15
    const int gg_ = r >> 2;
    const int uu  = r & 3;
    const int blk = blockIdx.x;
    const int grow = gg_ * HH + blk * 4 + uu;   // global gate-row

    // GEMM source pointers (fixed all slots)
    const float* wA = whh1 + grow * HH + s16 * 32;
    const float* wB = (s16 < 8 ? wih2 : whh2) + grow * HH + (s16 & 7) * 64;
    const float* wC = (s16 < 8 ? wih3 : whh3) + grow * HH + (s16 & 7) * 64;
    const float* hA = buf1 + s16 * 32 * 32;
    const float* hB = (s16 < 8 ? buf1 : buf2) + (s16 & 7) * 64 * 32;
    const float* hC = (s16 < 8 ? buf2 : buf3) + (s16 & 7) * 64 * 32;
    ull* prow = (ull*)&part[(s16 * 16 + r) * 34];

    // cell mapping (tid < 128): unit cu, batch cb
    const int cu  = tid >> 5;
    const int cb  = tid & 31;
    const int cunit = blk * 4 + cu;
    float c1 = 0.f, c2 = 0.f, c3 = 0.f, h3sum = 0.f;
    float bias2[4], bias3[4];
    if (tid < 128) {
#pragma unroll
        for (int g = 0; g < 4; ++g) {
            bias2[g] = b2[g * HH + cunit];
            bias3[g] = b3[g * HH + cunit];
        }
    }

    const unsigned sb1 = (unsigned)__cvta_generic_to_shared(buf1) + tid * 16;
    const unsigned sb2 = (unsigned)__cvta_generic_to_shared(buf2) + tid * 16;
    const unsigned sb3 = (unsigned)__cvta_generic_to_shared(buf3) + tid * 16;

    ull acc[16];

    for (int slot = 0; slot < NSLOT; ++slot) {
        const int rdp = (slot + 1) & 1;
        const int wrp = slot & 1;
        const bool v1 = slot < TT;
        const bool v2 = (slot >= 1) && (slot < TT + 1);
        const bool v3 = slot >= 2;

        // ---- async stage 3 h vectors (L2-coherent) ----
        {
            const char* s1 = (const char*)(g_hb1[rdp]) + tid * 16;
            const char* s2 = (const char*)(g_hb2[rdp]) + tid * 16;
            const char* s3 = (const char*)(g_hb3[rdp]) + tid * 16;
#pragma unroll
            for (int j = 0; j < 16; ++j) CP_ASYNC16(sb1 + j * 4096, s1 + j * 4096);
            CP_COMMIT();
#pragma unroll
            for (int j = 0; j < 16; ++j) CP_ASYNC16(sb2 + j * 4096, s2 + j * 4096);
            CP_COMMIT();
#pragma unroll
            for (int j = 0; j < 16; ++j) CP_ASYNC16(sb3 + j * 4096, s3 + j * 4096);
            CP_COMMIT();
        }
        // prefetch xp for cell A
        float xg0 = 0.f, xg1 = 0.f, xg2 = 0.f, xg3 = 0.f;
        if (v1 && tid < 128) {
            const float* xb = xp + (cb * TT + slot) * G4 + cunit;
            xg0 = __ldg(xb);
            xg1 = __ldg(xb + HH);
            xg2 = __ldg(xb + 2 * HH);
            xg3 = __ldg(xb + 3 * HH);
        }

        // ================= phase A : layer 1 =================
        CP_WAIT(2);
        __syncthreads();
        if (v1) {
            gslice(acc, wA, hA, 8);
#pragma unroll
            for (int j = 0; j < 16; ++j) prow[j] = acc[j];
        }
        __syncthreads();
        if (v1 && tid < 128) {
            float s0 = xg0, s1 = xg1, s2 = xg2, s3 = xg3;
#pragma unroll
            for (int s = 0; s < 16; ++s) {
                const float* pb = &part[(s * 16) * 34 + cb];
                s0 += pb[(0 * 4 + cu) * 34];
                s1 += pb[(1 * 4 + cu) * 34];
                s2 += pb[(2 * 4 + cu) * 34];
                s3 += pb[(3 * 4 + cu) * 34];
            }
            float ig = 1.f / (1.f + __expf(-s0));
            float fg = 1.f / (1.f + __expf(-s1));
            float gv = tanhf(s2);
            float og = 1.f / (1.f + __expf(-s3));
            c1 = fg * c1 + ig * gv;
            float hv = og * tanhf(c1);
            __stcg(&g_hb1[wrp][cunit * 32 + cb], hv);
        }

        // ================= phase B : layer 2 =================
        CP_WAIT(1);
        __syncthreads();
        if (v2) {
            gslice(acc, wB, hB, 16);
#pragma unroll
            for (int j = 0; j < 16; ++j) prow[j] = acc[j];
        }
        __syncthreads();
        if (v2 && tid < 128) {
            float s0 = bias2[0], s1 = bias2[1], s2 = bias2[2], s3 = bias2[3];
#pragma unroll
            for (int s = 0; s < 16; ++s) {
                const float* pb = &part[(s * 16) * 34 + cb];
                s0 += pb[(0 * 4 + cu) * 34];
                s1 += pb[(1 * 4 + cu) * 34];
                s2 += pb[(2 * 4 + cu) * 34];
                s3 += pb[(3 * 4 + cu) * 34];
            }
            float ig = 1.f / (1.f + __expf(-s0));
            float fg = 1.f / (1.f + __expf(-s1));
            float gv = tanhf(s2);
            float og = 1.f / (1.f + __expf(-s3));
            c2 = fg * c2 + ig * gv;
            float hv = og * tanhf(c2);
            __stcg(&g_hb2[wrp][cunit * 32 + cb], hv);
        }

        // ================= phase C : layer 3 =================
        CP_WAIT(0);
        __syncthreads();
        if (v3) {
            gslice(acc, wC, hC, 16);
#pragma unroll
            for (int j = 0; j < 16; ++j) prow[j] = acc[j];
        }
        __syncthreads();
        if (v3 && tid < 128) {
            float s0 = bias3[0], s1 = bias3[1], s2 = bias3[2], s3 = bias3[3];
#pragma unroll
            for (int s = 0; s < 16; ++s) {
                const float* pb = &part[(s * 16) * 34 + cb];
                s0 += pb[(0 * 4 + cu) * 34];
                s1 += pb[(1 * 4 + cu) * 34];
                s2 += pb[(2 * 4 + cu) * 34];
                s3 += pb[(3 * 4 + cu) * 34];
            }
            float ig = 1.f / (1.f + __expf(-s0));
            float fg = 1.f / (1.f + __expf(-s1));
            float gv = tanhf(s2);
            float og = 1.f / (1.f + __expf(-s3));
            c3 = fg * c3 + ig * gv;
            float hv = og * tanhf(c3);
            __stcg(&g_hb3[wrp][cunit * 32 + cb], hv);
            h3sum += hv;
        }

        grid_bar();
    }
    if (tid < 128)
        g_feat[cb * HH + cunit] = h3sum * (1.f / 512.f);
}

// --------------------------------- head ------------------------------------
__global__ __launch_bounds__(64) void head_kernel(
    const float* __restrict__ hw, const float* __restrict__ hb,
    float* __restrict__ outp)
{
    const int c = blockIdx.x, b = blockIdx.y;
    float s = 0.f;
    for (int k = threadIdx.x; k < HH; k += 64)
        s += g_feat[b * HH + k] * hw[c * HH + k];
    __shared__ float red[2];
#pragma unroll
    for (int o = 16; o; o >>= 1) s += __shfl_down_sync(0xffffffffu, s, o);
    if ((threadIdx.x & 31) == 0) red[threadIdx.x >> 5] = s;
    __syncthreads();
    if (threadIdx.x == 0) outp[b * NCLS + c] = red[0] + red[1] + hb[c];
}

// ------------------------------ launcher -----------------------------------
extern "C" void kernel_launch(void* const* d_in, const int* in_sizes, int n_in,
                              void* d_out, int out_size)
{
    const float* x_emg  = (const float*)d_in[0];
    const float* conv_w = (const float*)d_in[1];
    const float* gamma  = (const float*)d_in[2];
    const float* beta   = (const float*)d_in[3];
    const float *w_ih[3], *w_hh[3], *bi[3], *head_w, *head_b;

    if (in_sizes[4] == 4 * HH * FF) {          // signature order
        for (int l = 0; l < 3; ++l) {
            w_ih[l] = (const float*)d_in[4 + 3 * l];
            w_hh[l] = (const float*)d_in[5 + 3 * l];
            bi[l]   = (const float*)d_in[6 + 3 * l];
        }
        head_w = (const float*)d_in[13];
        head_b = (const float*)d_in[14];
    } else {                                    // dict order
        head_w = (const float*)d_in[4];
        head_b = (const float*)d_in[5];
        for (int l = 0; l < 3; ++l) {
            w_ih[l] = (const float*)d_in[6 + 3 * l];
            w_hh[l] = (const float*)d_in[7 + 3 * l];
            bi[l]   = (const float*)d_in[8 + 3 * l];
        }
    }
    float* out = (float*)d_out;

    cudaFuncSetAttribute(conv_kernel,
        cudaFuncAttributeMaxDynamicSharedMemorySize, CONV_SMEM);
    cudaFuncSetAttribute(fused_rec_kernel,
        cudaFuncAttributeMaxDynamicSharedMemorySize, FSMEM);

    float* g_xp_p;   cudaGetSymbolAddress((void**)&g_xp_p, g_xp);
    float* g_xt_p;   cudaGetSymbolAddress((void**)&g_xt_p, g_xt);

    conv_kernel<<<dim3(TT / 128, BB), 256, CONV_SMEM>>>(x_emg, conv_w);
    gn_stats_kernel<<<BB * GG, 256>>>();
    gn_apply_kernel<<<dim3(TT / 32, FF / 32, BB), 256>>>(gamma, beta);

    // layer-1 input projections (bias folded in)
    gemm_kernel<<<dim3(G4 / 64, BB * TT / 64), 256>>>(
        g_xt_p, w_ih[0], bi[0], g_xp_p, FF);

    zero_h_kernel<<<128, 256>>>();
    fused_rec_kernel<<<RNB, 256, FSMEM>>>(
        g_xp_p, w_hh[0], w_ih[1], w_hh[1], bi[1], w_ih[2], w_hh[2], bi[2]);

    head_kernel<<<dim3(NCLS, BB), 64>>>(head_w, head_b, out);
}

// round 6
// speedup vs baseline: 1.1298x; 1.0007x over previous
#include <cuda_runtime.h>
#include <math.h>

typedef unsigned long long ull;

// ---------------------------------------------------------------------------
// MetaCNNLSTM: conv1d(64->256,k9,pad4) -> GN(8)+ReLU -> 3x LSTM(512) -> mean
// pool -> linear head.  B=32, T=512, fp32.
// Wavefront-fused recurrence: one persistent kernel runs all 3 LSTM layers,
// slot s computes (L1 t=s, L2 t=s-1, L3 t=s-2). 514 grid barriers total.
// ---------------------------------------------------------------------------
#define BB   32
#define CIN  64
#define TT   512
#define FF   256
#define GG   8
#define HH   512
#define G4   2048
#define NCLS 50
#define RNB  128    // persistent blocks (must be co-resident; <= 152 SMs)
#define NSLOT (TT + 2)

// ------------------------- scratch (static device globals) -----------------
__device__ float   g_conv[BB * FF * TT];     // conv out (B,F,T)
__device__ float   g_xt[BB * TT * FF];       // GN+ReLU, (B*T, F)
__device__ float   g_xp[BB * TT * G4];       // layer-1 input projections
__device__ float   g_hb1[2][HH * BB];        // h1 ping-pong [unit][batch]
__device__ float   g_hb2[2][HH * BB];        // h2 ping-pong
__device__ float   g_hb3[2][HH * BB];        // h3 ping-pong
__device__ float   g_feat[BB * HH];          // pooled features
__device__ float2  g_stat[BB * GG];          // GN (mean, rstd)
__device__ unsigned g_cnt;                   // global barrier count
__device__ unsigned g_gen;                   // global barrier generation

// ------------------------- f32x2 / async helpers ----------------------------
__device__ __forceinline__ void fma2(ull& d, ull a, ull b) {
    asm("fma.rn.f32x2 %0, %1, %2, %0;" : "+l"(d) : "l"(a), "l"(b));
}
__device__ __forceinline__ ull pk2(float x) {
    ull r; asm("mov.b64 %0, {%1, %1};" : "=l"(r) : "f"(x)); return r;
}
#define CP_ASYNC16(dst_u32, src_ptr) \
    asm volatile("cp.async.cg.shared.global [%0], [%1], 16;" \
                 :: "r"(dst_u32), "l"(src_ptr))
#define CP_COMMIT() asm volatile("cp.async.commit_group;")
#define CP_WAIT(n)  asm volatile("cp.async.wait_group " #n ";" ::: "memory")

// ------------------------------- conv1d ------------------------------------
#define CONV_SMEM ((64 * 136 + 8 * 64 * 9) * 4)
__global__ __launch_bounds__(256) void conv_kernel(
    const float* __restrict__ x, const float* __restrict__ w)
{
    extern __shared__ float sm[];
    float* xs = sm;              // [64][136]
    float* ws = sm + 64 * 136;   // [8][64][9]
    const int b   = blockIdx.y;
    const int t0  = blockIdx.x * 128;
    const int tid = threadIdx.x;

    for (int i = tid; i < 64 * 136; i += 256) {
        int c = i / 136, j = i - c * 136;
        int t = t0 - 4 + j;
        xs[i] = (t >= 0 && t < TT) ? x[(b * CIN + c) * TT + t] : 0.f;
    }
    const int lane = tid & 31;
    const int wf   = tid >> 5;
    const int tl   = lane * 4;

    for (int fc = 0; fc < FF; fc += 8) {
        __syncthreads();
        for (int i = tid; i < 8 * 64 * 9; i += 256)
            ws[i] = w[fc * 64 * 9 + i];
        __syncthreads();
        const int f = fc + wf;
        float a0 = 0.f, a1 = 0.f, a2 = 0.f, a3 = 0.f;
        for (int c = 0; c < 64; ++c) {
            const float* xr = &xs[c * 136 + tl];
            const float* wr = &ws[(wf * 64 + c) * 9];
            float4 p0 = *(const float4*)(xr);
            float4 p1 = *(const float4*)(xr + 4);
            float4 p2 = *(const float4*)(xr + 8);
            float xv[12] = {p0.x, p0.y, p0.z, p0.w, p1.x, p1.y, p1.z, p1.w,
                            p2.x, p2.y, p2.z, p2.w};
#pragma unroll
            for (int k = 0; k < 9; ++k) {
                float wk = wr[k];
                a0 += wk * xv[k];
                a1 += wk * xv[k + 1];
                a2 += wk * xv[k + 2];
                a3 += wk * xv[k + 3];
            }
        }
        *(float4*)&g_conv[(b * FF + f) * TT + t0 + tl] =
            make_float4(a0, a1, a2, a3);
    }
}

// ------------------------------ groupnorm stats -----------------------------
__global__ __launch_bounds__(256) void gn_stats_kernel()
{
    const int b = blockIdx.x >> 3, g = blockIdx.x & 7;
    __shared__ float ssum[256], ssq[256];
    const int tid = threadIdx.x;
    const float* base = g_conv + (b * FF + g * 32) * TT;
    float s = 0.f, q = 0.f;
    for (int i = tid; i < 32 * TT; i += 256) {
        float v = base[i];
        s += v; q += v * v;
    }
    ssum[tid] = s; ssq[tid] = q;
    __syncthreads();
    for (int o = 128; o > 0; o >>= 1) {
        if (tid < o) { ssum[tid] += ssum[tid + o]; ssq[tid] += ssq[tid + o]; }
        __syncthreads();
    }
    if (tid == 0) {
        float mean = ssum[0] * (1.f / 16384.f);
        float var  = ssq[0] * (1.f / 16384.f) - mean * mean;
        g_stat[b * GG + g] = make_float2(mean, rsqrtf(var + 1e-5f));
    }
}

// -------- GN apply + ReLU + transpose (B,F,T) -> (B*T, F) -------------------
__global__ __launch_bounds__(256) void gn_apply_kernel(
    const float* __restrict__ gamma, const float* __restrict__ beta)
{
    __shared__ float tile[32][33];
    const int b  = blockIdx.z;
    const int f0 = blockIdx.y * 32;
    const int t0 = blockIdx.x * 32;
    const int tx = threadIdx.x & 31, ty = threadIdx.x >> 5;
#pragma unroll
    for (int j = 0; j < 4; ++j) {
        int f = f0 + ty + j * 8;
        float2 st = g_stat[b * GG + (f >> 5)];
        float v = g_conv[(b * FF + f) * TT + t0 + tx];
        v = (v - st.x) * st.y * gamma[f] + beta[f];
        tile[ty + j * 8][tx] = fmaxf(v, 0.f);
    }
    __syncthreads();
#pragma unroll
    for (int j = 0; j < 4; ++j) {
        int t = t0 + ty + j * 8;
        g_xt[(b * TT + t) * FF + f0 + tx] = tile[tx][ty + j * 8];
    }
}

// --------------------- projection GEMM: C = A @ B^T + bias ------------------
// (layer-1 only now).  64x64 tile, 4x4 per thread (R2 version, known-good).
__global__ __launch_bounds__(256) void gemm_kernel(
    const float* __restrict__ A, const float* __restrict__ Bm,
    const float* __restrict__ bias, float* __restrict__ C, int Ka)
{
    __shared__ float As[16][64];
    __shared__ float Bs[16][64];
    const int bm = blockIdx.y * 64, bn = blockIdx.x * 64;
    const int tid = threadIdx.x;
    const int lm  = tid >> 2;
    const int lk4 = (tid & 3) * 4;
    const int tm  = (tid & 15) * 4;
    const int tn  = (tid >> 4) * 4;

    float acc[4][4];
#pragma unroll
    for (int i = 0; i < 4; ++i)
#pragma unroll
        for (int j = 0; j < 4; ++j) acc[i][j] = 0.f;

    for (int ko = 0; ko < Ka; ko += 16) {
        float4 av = *(const float4*)&A[(bm + lm) * Ka + ko + lk4];
        float4 bv = *(const float4*)&Bm[(bn + lm) * Ka + ko + lk4];
        __syncthreads();
        As[lk4 + 0][lm] = av.x; As[lk4 + 1][lm] = av.y;
        As[lk4 + 2][lm] = av.z; As[lk4 + 3][lm] = av.w;
        Bs[lk4 + 0][lm] = bv.x; Bs[lk4 + 1][lm] = bv.y;
        Bs[lk4 + 2][lm] = bv.z; Bs[lk4 + 3][lm] = bv.w;
        __syncthreads();
#pragma unroll
        for (int k = 0; k < 16; ++k) {
            float4 a4 = *(const float4*)&As[k][tm];
            float4 b4 = *(const float4*)&Bs[k][tn];
            float am[4] = {a4.x, a4.y, a4.z, a4.w};
            float bn4[4] = {b4.x, b4.y, b4.z, b4.w};
#pragma unroll
            for (int i = 0; i < 4; ++i)
#pragma unroll
                for (int j = 0; j < 4; ++j) acc[i][j] += am[i] * bn4[j];
        }
    }
#pragma unroll
    for (int i = 0; i < 4; ++i) {
        int row = bm + tm + i;
#pragma unroll
        for (int j = 0; j < 4; ++j)
            C[row * G4 + bn + tn + j] = acc[i][j] + bias[bn + tn + j];
    }
}

// ----------------------- zero ping-pong h buffers ---------------------------
__global__ void zero_h_kernel()
{
    int i = blockIdx.x * 256 + threadIdx.x;   // grid 128 -> 32768
    ((float*)g_hb1)[i] = 0.f;
    ((float*)g_hb2)[i] = 0.f;
    ((float*)g_hb3)[i] = 0.f;
}

// ------------------------- grid barrier -------------------------------------
__device__ __forceinline__ void grid_bar()
{
    __syncthreads();
    if (threadIdx.x == 0) {
        unsigned gen = *(volatile unsigned*)&g_gen;
        __threadfence();
        if (atomicAdd(&g_cnt, 1u) == RNB - 1) {
            g_cnt = 0;
            __threadfence();
            atomicAdd(&g_gen, 1u);
        } else {
            while (*(volatile unsigned*)&g_gen == gen) __nanosleep(32);
        }
    }
    __syncthreads();
}

// -------------------- per-thread GEMM slice (f32x2) -------------------------
// acc[i] accumulates batch pair (2i, 2i+1) for this thread's row & k-slice.
__device__ __forceinline__ void gslice(ull* acc, const float* __restrict__ w,
                                       const float* hbase, int nk4)
{
#pragma unroll
    for (int i = 0; i < 16; ++i) acc[i] = 0ull;
#pragma unroll 4
    for (int k4 = 0; k4 < nk4; ++k4) {
        float4 w4 = __ldg((const float4*)(w + k4 * 4));
        float wa[4] = {w4.x, w4.y, w4.z, w4.w};
#pragma unroll
        for (int j = 0; j < 4; ++j) {
            ull wv = pk2(wa[j]);
            const ulonglong2* hp =
                (const ulonglong2*)(hbase + (k4 * 4 + j) * 32);
#pragma unroll
            for (int q = 0; q < 8; ++q) {
                ulonglong2 hv = hp[q];
                fma2(acc[2 * q],     wv, hv.x);
                fma2(acc[2 * q + 1], wv, hv.y);
            }
        }
    }
}

// ------------------- fused 3-layer wavefront recurrence ---------------------
// smem: buf1/2/3: [512 units][32 batch] staged h vectors (64KB each)
//       part: [16 slice][16 row][34]  (34KB)
#define FSMEM ((3 * HH * BB + 16 * 16 * 34) * 4)
__global__ __launch_bounds__(256) void fused_rec_kernel(
    const float* __restrict__ xp,
    const float* __restrict__ whh1,
    const float* __restrict__ wih2, const float* __restrict__ whh2,
    const float* __restrict__ b2,
    const float* __restrict__ wih3, const float* __restrict__ whh3,
    const float* __restrict__ b3)
{
    extern __shared__ float sm[];
    float* buf1 = sm;                  // h1[s-1]
    float* buf2 = sm + HH * BB;        // h2[s-2]
    float* buf3 = sm + 2 * HH * BB;    // h3[s-3]
    float* part = sm + 3 * HH * BB;    // [16][16][34]

    const int tid = threadIdx.x;
    const int r   = tid & 15;          // gemm row 0..15 (= gate*4 + unit)
    const int s16 = tid >> 4;          // k-slice 0..15
    const int gg_ = r >> 2;
    const int uu  = r & 3;
    const int blk = blockIdx.x;
    const int grow = gg_ * HH + blk * 4 + uu;   // global gate-row

    // GEMM source pointers (fixed all slots)
    const float* wA = whh1 + grow * HH + s16 * 32;
    const float* wB = (s16 < 8 ? wih2 : whh2) + grow * HH + (s16 & 7) * 64;
    const float* wC = (s16 < 8 ? wih3 : whh3) + grow * HH + (s16 & 7) * 64;
    const float* hA = buf1 + s16 * 32 * 32;
    const float* hB = (s16 < 8 ? buf1 : buf2) + (s16 & 7) * 64 * 32;
    const float* hC = (s16 < 8 ? buf2 : buf3) + (s16 & 7) * 64 * 32;
    ull* prow = (ull*)&part[(s16 * 16 + r) * 34];

    // cell mapping (tid < 128): unit cu, batch cb
    const int cu  = tid >> 5;
    const int cb  = tid & 31;
    const int cunit = blk * 4 + cu;
    float c1 = 0.f, c2 = 0.f, c3 = 0.f, h3sum = 0.f;
    float bias2[4], bias3[4];
    if (tid < 128) {
#pragma unroll
        for (int g = 0; g < 4; ++g) {
            bias2[g] = b2[g * HH + cunit];
            bias3[g] = b3[g * HH + cunit];
        }
    }

    const unsigned sb1 = (unsigned)__cvta_generic_to_shared(buf1) + tid * 16;
    const unsigned sb2 = (unsigned)__cvta_generic_to_shared(buf2) + tid * 16;
    const unsigned sb3 = (unsigned)__cvta_generic_to_shared(buf3) + tid * 16;

    ull acc[16];

    for (int slot = 0; slot < NSLOT; ++slot) {
        const int rdp = (slot + 1) & 1;
        const int wrp = slot & 1;
        const bool v1 = slot < TT;
        const bool v2 = (slot >= 1) && (slot < TT + 1);
        const bool v3 = slot >= 2;

        // ---- async stage 3 h vectors (L2-coherent) ----
        {
            const char* s1 = (const char*)(g_hb1[rdp]) + tid * 16;
            const char* s2 = (const char*)(g_hb2[rdp]) + tid * 16;
            const char* s3 = (const char*)(g_hb3[rdp]) + tid * 16;
#pragma unroll
            for (int j = 0; j < 16; ++j) CP_ASYNC16(sb1 + j * 4096, s1 + j * 4096);
            CP_COMMIT();
#pragma unroll
            for (int j = 0; j < 16; ++j) CP_ASYNC16(sb2 + j * 4096, s2 + j * 4096);
            CP_COMMIT();
#pragma unroll
            for (int j = 0; j < 16; ++j) CP_ASYNC16(sb3 + j * 4096, s3 + j * 4096);
            CP_COMMIT();
        }
        // prefetch xp for cell A
        float xg0 = 0.f, xg1 = 0.f, xg2 = 0.f, xg3 = 0.f;
        if (v1 && tid < 128) {
            const float* xb = xp + (cb * TT + slot) * G4 + cunit;
            xg0 = __ldg(xb);
            xg1 = __ldg(xb + HH);
            xg2 = __ldg(xb + 2 * HH);
            xg3 = __ldg(xb + 3 * HH);
        }

        // ================= phase A : layer 1 =================
        CP_WAIT(2);
        __syncthreads();
        if (v1) {
            gslice(acc, wA, hA, 8);
#pragma unroll
            for (int j = 0; j < 16; ++j) prow[j] = acc[j];
        }
        __syncthreads();
        if (v1 && tid < 128) {
            float s0 = xg0, s1 = xg1, s2 = xg2, s3 = xg3;
#pragma unroll
            for (int s = 0; s < 16; ++s) {
                const float* pb = &part[(s * 16) * 34 + cb];
                s0 += pb[(0 * 4 + cu) * 34];
                s1 += pb[(1 * 4 + cu) * 34];
                s2 += pb[(2 * 4 + cu) * 34];
                s3 += pb[(3 * 4 + cu) * 34];
            }
            float ig = 1.f / (1.f + __expf(-s0));
            float fg = 1.f / (1.f + __expf(-s1));
            float gv = tanhf(s2);
            float og = 1.f / (1.f + __expf(-s3));
            c1 = fg * c1 + ig * gv;
            float hv = og * tanhf(c1);
            __stcg(&g_hb1[wrp][cunit * 32 + cb], hv);
        }

        // ================= phase B : layer 2 =================
        CP_WAIT(1);
        __syncthreads();
        if (v2) {
            gslice(acc, wB, hB, 16);
#pragma unroll
            for (int j = 0; j < 16; ++j) prow[j] = acc[j];
        }
        __syncthreads();
        if (v2 && tid < 128) {
            float s0 = bias2[0], s1 = bias2[1], s2 = bias2[2], s3 = bias2[3];
#pragma unroll
            for (int s = 0; s < 16; ++s) {
                const float* pb = &part[(s * 16) * 34 + cb];
                s0 += pb[(0 * 4 + cu) * 34];
                s1 += pb[(1 * 4 + cu) * 34];
                s2 += pb[(2 * 4 + cu) * 34];
                s3 += pb[(3 * 4 + cu) * 34];
            }
            float ig = 1.f / (1.f + __expf(-s0));
            float fg = 1.f / (1.f + __expf(-s1));
            float gv = tanhf(s2);
            float og = 1.f / (1.f + __expf(-s3));
            c2 = fg * c2 + ig * gv;
            float hv = og * tanhf(c2);
            __stcg(&g_hb2[wrp][cunit * 32 + cb], hv);
        }

        // ================= phase C : layer 3 =================
        CP_WAIT(0);
        __syncthreads();
        if (v3) {
            gslice(acc, wC, hC, 16);
#pragma unroll
            for (int j = 0; j < 16; ++j) prow[j] = acc[j];
        }
        __syncthreads();
        if (v3 && tid < 128) {
            float s0 = bias3[0], s1 = bias3[1], s2 = bias3[2], s3 = bias3[3];
#pragma unroll
            for (int s = 0; s < 16; ++s) {
                const float* pb = &part[(s * 16) * 34 + cb];
                s0 += pb[(0 * 4 + cu) * 34];
                s1 += pb[(1 * 4 + cu) * 34];
                s2 += pb[(2 * 4 + cu) * 34];
                s3 += pb[(3 * 4 + cu) * 34];
            }
            float ig = 1.f / (1.f + __expf(-s0));
            float fg = 1.f / (1.f + __expf(-s1));
            float gv = tanhf(s2);
            float og = 1.f / (1.f + __expf(-s3));
            c3 = fg * c3 + ig * gv;
            float hv = og * tanhf(c3);
            __stcg(&g_hb3[wrp][cunit * 32 + cb], hv);
            h3sum += hv;
        }

        grid_bar();
    }
    if (tid < 128)
        g_feat[cb * HH + cunit] = h3sum * (1.f / 512.f);
}

// --------------------------------- head ------------------------------------
__global__ __launch_bounds__(64) void head_kernel(
    const float* __restrict__ hw, const float* __restrict__ hb,
    float* __restrict__ outp)
{
    const int c = blockIdx.x, b = blockIdx.y;
    float s = 0.f;
    for (int k = threadIdx.x; k < HH; k += 64)
        s += g_feat[b * HH + k] * hw[c * HH + k];
    __shared__ float red[2];
#pragma unroll
    for (int o = 16; o; o >>= 1) s += __shfl_down_sync(0xffffffffu, s, o);
    if ((threadIdx.x & 31) == 0) red[threadIdx.x >> 5] = s;
    __syncthreads();
    if (threadIdx.x == 0) outp[b * NCLS + c] = red[0] + red[1] + hb[c];
}

// ------------------------------ launcher -----------------------------------
extern "C" void kernel_launch(void* const* d_in, const int* in_sizes, int n_in,
                              void* d_out, int out_size)
{
    const float* x_emg  = (const float*)d_in[0];
    const float* conv_w = (const float*)d_in[1];
    const float* gamma  = (const float*)d_in[2];
    const float* beta   = (const float*)d_in[3];
    const float *w_ih[3], *w_hh[3], *bi[3], *head_w, *head_b;

    if (in_sizes[4] == 4 * HH * FF) {          // signature order
        for (int l = 0; l < 3; ++l) {
            w_ih[l] = (const float*)d_in[4 + 3 * l];
            w_hh[l] = (const float*)d_in[5 + 3 * l];
            bi[l]   = (const float*)d_in[6 + 3 * l];
        }
        head_w = (const float*)d_in[13];
        head_b = (const float*)d_in[14];
    } else {                                    // dict order
        head_w = (const float*)d_in[4];
        head_b = (const float*)d_in[5];
        for (int l = 0; l < 3; ++l) {
            w_ih[l] = (const float*)d_in[6 + 3 * l];
            w_hh[l] = (const float*)d_in[7 + 3 * l];
            bi[l]   = (const float*)d_in[8 + 3 * l];
        }
    }
    float* out = (float*)d_out;

    cudaFuncSetAttribute(conv_kernel,
        cudaFuncAttributeMaxDynamicSharedMemorySize, CONV_SMEM);
    cudaFuncSetAttribute(fused_rec_kernel,
        cudaFuncAttributeMaxDynamicSharedMemorySize, FSMEM);

    float* g_xp_p;   cudaGetSymbolAddress((void**)&g_xp_p, g_xp);
    float* g_xt_p;   cudaGetSymbolAddress((void**)&g_xt_p, g_xt);

    conv_kernel<<<dim3(TT / 128, BB), 256, CONV_SMEM>>>(x_emg, conv_w);
    gn_stats_kernel<<<BB * GG, 256>>>();
    gn_apply_kernel<<<dim3(TT / 32, FF / 32, BB), 256>>>(gamma, beta);

    // layer-1 input projections (bias folded in)
    gemm_kernel<<<dim3(G4 / 64, BB * TT / 64), 256>>>(
        g_xt_p, w_ih[0], bi[0], g_xp_p, FF);

    zero_h_kernel<<<128, 256>>>();
    fused_rec_kernel<<<RNB, 256, FSMEM>>>(
        g_xp_p, w_hh[0], w_ih[1], w_hh[1], bi[1], w_ih[2], w_hh[2], bi[2]);

    head_kernel<<<dim3(NCLS, BB), 64>>>(head_w, head_b, out);
}

// round 7
// speedup vs baseline: 1.3089x; 1.1585x over previous
#include <cuda_runtime.h>
#include <math.h>

typedef unsigned long long ull;

#define BB   32
#define CIN  64
#define TT   512
#define FF   256
#define GG   8
#define HH   512
#define G4   2048
#define NCLS 50
#define RNB  128
#define NSLOT (TT + 2)
#define PSTR 34
#define PSZ  (16 * 16 * PSTR)

// ------------------------- scratch -----------------------------------------
__device__ float   g_conv[BB * FF * TT];
__device__ float   g_xt[BB * TT * FF];
__device__ float   g_xp[BB * TT * G4];
__device__ float   g_hb1[2][BB * HH];    // [parity][b*HH + unit]
__device__ float   g_hb2[2][BB * HH];
__device__ float   g_hb3[2][BB * HH];
__device__ float   g_feat[BB * HH];
__device__ float2  g_stat[BB * GG];
__device__ unsigned g_cnt;
__device__ unsigned g_gen;

// ------------------------- helpers -----------------------------------------
__device__ __forceinline__ void fma2(ull& d, ull a, ull b) {
    asm("fma.rn.f32x2 %0, %1, %2, %0;" : "+l"(d) : "l"(a), "l"(b));
}
union UF2 { ull u; float2 f; };
#define CP_ASYNC16(dst_u32, src_ptr) \
    asm volatile("cp.async.cg.shared.global [%0], [%1], 16;" \
                 :: "r"(dst_u32), "l"(src_ptr))
#define CP_COMMIT() asm volatile("cp.async.commit_group;")
#define CP_WAIT(n)  asm volatile("cp.async.wait_group " #n ";" ::: "memory")

// ------------------------------- conv1d ------------------------------------
#define CONV_SMEM ((64 * 136 + 8 * 64 * 9) * 4)
__global__ __launch_bounds__(256) void conv_kernel(
    const float* __restrict__ x, const float* __restrict__ w)
{
    extern __shared__ float sm[];
    float* xs = sm;
    float* ws = sm + 64 * 136;
    const int b   = blockIdx.y;
    const int t0  = blockIdx.x * 128;
    const int tid = threadIdx.x;

    for (int i = tid; i < 64 * 136; i += 256) {
        int c = i / 136, j = i - c * 136;
        int t = t0 - 4 + j;
        xs[i] = (t >= 0 && t < TT) ? x[(b * CIN + c) * TT + t] : 0.f;
    }
    const int lane = tid & 31;
    const int wf   = tid >> 5;
    const int tl   = lane * 4;

    for (int fc = 0; fc < FF; fc += 8) {
        __syncthreads();
        for (int i = tid; i < 8 * 64 * 9; i += 256)
            ws[i] = w[fc * 64 * 9 + i];
        __syncthreads();
        const int f = fc + wf;
        float a0 = 0.f, a1 = 0.f, a2 = 0.f, a3 = 0.f;
        for (int c = 0; c < 64; ++c) {
            const float* xr = &xs[c * 136 + tl];
            const float* wr = &ws[(wf * 64 + c) * 9];
            float4 p0 = *(const float4*)(xr);
            float4 p1 = *(const float4*)(xr + 4);
            float4 p2 = *(const float4*)(xr + 8);
            float xv[12] = {p0.x, p0.y, p0.z, p0.w, p1.x, p1.y, p1.z, p1.w,
                            p2.x, p2.y, p2.z, p2.w};
#pragma unroll
            for (int k = 0; k < 9; ++k) {
                float wk = wr[k];
                a0 += wk * xv[k];
                a1 += wk * xv[k + 1];
                a2 += wk * xv[k + 2];
                a3 += wk * xv[k + 3];
            }
        }
        *(float4*)&g_conv[(b * FF + f) * TT + t0 + tl] =
            make_float4(a0, a1, a2, a3);
    }
}

// ------------------------------ groupnorm -----------------------------------
__global__ __launch_bounds__(256) void gn_stats_kernel()
{
    const int b = blockIdx.x >> 3, g = blockIdx.x & 7;
    __shared__ float ssum[256], ssq[256];
    const int tid = threadIdx.x;
    const float* base = g_conv + (b * FF + g * 32) * TT;
    float s = 0.f, q = 0.f;
    for (int i = tid; i < 32 * TT; i += 256) {
        float v = base[i];
        s += v; q += v * v;
    }
    ssum[tid] = s; ssq[tid] = q;
    __syncthreads();
    for (int o = 128; o > 0; o >>= 1) {
        if (tid < o) { ssum[tid] += ssum[tid + o]; ssq[tid] += ssq[tid + o]; }
        __syncthreads();
    }
    if (tid == 0) {
        float mean = ssum[0] * (1.f / 16384.f);
        float var  = ssq[0] * (1.f / 16384.f) - mean * mean;
        g_stat[b * GG + g] = make_float2(mean, rsqrtf(var + 1e-5f));
    }
}

__global__ __launch_bounds__(256) void gn_apply_kernel(
    const float* __restrict__ gamma, const float* __restrict__ beta)
{
    __shared__ float tile[32][33];
    const int b  = blockIdx.z;
    const int f0 = blockIdx.y * 32;
    const int t0 = blockIdx.x * 32;
    const int tx = threadIdx.x & 31, ty = threadIdx.x >> 5;
#pragma unroll
    for (int j = 0; j < 4; ++j) {
        int f = f0 + ty + j * 8;
        float2 st = g_stat[b * GG + (f >> 5)];
        float v = g_conv[(b * FF + f) * TT + t0 + tx];
        v = (v - st.x) * st.y * gamma[f] + beta[f];
        tile[ty + j * 8][tx] = fmaxf(v, 0.f);
    }
    __syncthreads();
#pragma unroll
    for (int j = 0; j < 4; ++j) {
        int t = t0 + ty + j * 8;
        g_xt[(b * TT + t) * FF + f0 + tx] = tile[tx][ty + j * 8];
    }
}

// --------------------- projection GEMM (layer 1) ----------------------------
__global__ __launch_bounds__(256) void gemm_kernel(
    const float* __restrict__ A, const float* __restrict__ Bm,
    const float* __restrict__ bias, float* __restrict__ C, int Ka)
{
    __shared__ float As[16][64];
    __shared__ float Bs[16][64];
    const int bm = blockIdx.y * 64, bn = blockIdx.x * 64;
    const int tid = threadIdx.x;
    const int lm  = tid >> 2;
    const int lk4 = (tid & 3) * 4;
    const int tm  = (tid & 15) * 4;
    const int tn  = (tid >> 4) * 4;

    float acc[4][4];
#pragma unroll
    for (int i = 0; i < 4; ++i)
#pragma unroll
        for (int j = 0; j < 4; ++j) acc[i][j] = 0.f;

    for (int ko = 0; ko < Ka; ko += 16) {
        float4 av = *(const float4*)&A[(bm + lm) * Ka + ko + lk4];
        float4 bv = *(const float4*)&Bm[(bn + lm) * Ka + ko + lk4];
        __syncthreads();
        As[lk4 + 0][lm] = av.x; As[lk4 + 1][lm] = av.y;
        As[lk4 + 2][lm] = av.z; As[lk4 + 3][lm] = av.w;
        Bs[lk4 + 0][lm] = bv.x; Bs[lk4 + 1][lm] = bv.y;
        Bs[lk4 + 2][lm] = bv.z; Bs[lk4 + 3][lm] = bv.w;
        __syncthreads();
#pragma unroll
        for (int k = 0; k < 16; ++k) {
            float4 a4 = *(const float4*)&As[k][tm];
            float4 b4 = *(const float4*)&Bs[k][tn];
            float am[4] = {a4.x, a4.y, a4.z, a4.w};
            float bn4[4] = {b4.x, b4.y, b4.z, b4.w};
#pragma unroll
            for (int i = 0; i < 4; ++i)
#pragma unroll
                for (int j = 0; j < 4; ++j) acc[i][j] += am[i] * bn4[j];
        }
    }
#pragma unroll
    for (int i = 0; i < 4; ++i) {
        int row = bm + tm + i;
#pragma unroll
        for (int j = 0; j < 4; ++j)
            C[row * G4 + bn + tn + j] = acc[i][j] + bias[bn + tn + j];
    }
}

// ----------------------- zero h buffers -------------------------------------
__global__ void zero_h_kernel()
{
    int i = blockIdx.x * 256 + threadIdx.x;   // grid 128 -> 32768 (both parities)
    ((float*)g_hb1)[i] = 0.f;
    ((float*)g_hb2)[i] = 0.f;
    ((float*)g_hb3)[i] = 0.f;
}

// ------------------------- grid barrier -------------------------------------
__device__ __forceinline__ void grid_bar()
{
    __syncthreads();
    if (threadIdx.x == 0) {
        unsigned gen = *(volatile unsigned*)&g_gen;
        __threadfence();
        if (atomicAdd(&g_cnt, 1u) == RNB - 1) {
            g_cnt = 0;
            __threadfence();
            atomicAdd(&g_gen, 1u);
        } else {
            while (*(volatile unsigned*)&g_gen == gen) __nanosleep(32);
        }
    }
    __syncthreads();
}

// ------------- per-thread GEMM slice, both operands packed along k ----------
// 8 rows (2 gates x 4 units) x 2 batch rows, k-slice of nk4 16B-granules.
__device__ __forceinline__ void gphase(ull acc[8][2],
    const float* __restrict__ w0, const float* __restrict__ w1,
    const float* hr0, const float* hr1, int swz, int nk4)
{
#pragma unroll
    for (int i = 0; i < 8; ++i) { acc[i][0] = 0ull; acc[i][1] = 0ull; }
#pragma unroll 4
    for (int l = 0; l < nk4; ++l) {
        const int lp = ((l & ~7) | ((l & 7) ^ swz)) * 4;
        ulonglong2 h0 = *(const ulonglong2*)(hr0 + lp);
        ulonglong2 h1 = *(const ulonglong2*)(hr1 + lp);
#pragma unroll
        for (int i = 0; i < 4; ++i) {
            ulonglong2 wv = __ldg((const ulonglong2*)(w0 + i * 512 + l * 4));
            fma2(acc[i][0], wv.x, h0.x); fma2(acc[i][0], wv.y, h0.y);
            fma2(acc[i][1], wv.x, h1.x); fma2(acc[i][1], wv.y, h1.y);
        }
#pragma unroll
        for (int i = 0; i < 4; ++i) {
            ulonglong2 wv = __ldg((const ulonglong2*)(w1 + i * 512 + l * 4));
            fma2(acc[4 + i][0], wv.x, h0.x); fma2(acc[4 + i][0], wv.y, h0.y);
            fma2(acc[4 + i][1], wv.x, h1.x); fma2(acc[4 + i][1], wv.y, h1.y);
        }
    }
}

__device__ __forceinline__ void store_part(float* part, ull acc[8][2],
                                           int ks, int rg, int bq)
{
#pragma unroll
    for (int i = 0; i < 8; ++i) {
        UF2 t0, t1; t0.u = acc[i][0]; t1.u = acc[i][1];
        *(float2*)&part[(ks * 16 + rg * 8 + i) * PSTR + 2 * bq] =
            make_float2(t0.f.x + t0.f.y, t1.f.x + t1.f.y);
    }
}

__device__ __forceinline__ float4 cell_sum(const float* part, int cu, int cb)
{
    float4 s = make_float4(0.f, 0.f, 0.f, 0.f);
#pragma unroll
    for (int k = 0; k < 16; ++k) {
        const float* pb = part + (k * 16) * PSTR + cb;
        s.x += pb[(0 + cu) * PSTR];
        s.y += pb[(4 + cu) * PSTR];
        s.z += pb[(8 + cu) * PSTR];
        s.w += pb[(12 + cu) * PSTR];
    }
    return s;
}

__device__ __forceinline__ float lstm_cell(float4 g, float& c)
{
    float ig = 1.f / (1.f + __expf(-g.x));
    float fg = 1.f / (1.f + __expf(-g.y));
    float gv = tanhf(g.z);
    float og = 1.f / (1.f + __expf(-g.w));
    c = fg * c + ig * gv;
    return og * tanhf(c);
}

// ------------------- fused 3-layer wavefront recurrence ---------------------
// smem: buf1/2/3 [32 b][512 k] (64KB each, pair-swizzled) + part (34KB)
#define FSMEM ((3 * HH * BB + PSZ) * 4)
__global__ __launch_bounds__(512, 1) void fused_rec_kernel(
    const float* __restrict__ xp,
    const float* __restrict__ whh1,
    const float* __restrict__ wih2, const float* __restrict__ whh2,
    const float* __restrict__ b2,
    const float* __restrict__ wih3, const float* __restrict__ whh3,
    const float* __restrict__ b3)
{
    extern __shared__ float sm[];
    float* buf1 = sm;
    float* buf2 = sm + HH * BB;
    float* buf3 = sm + 2 * HH * BB;
    float* part = sm + 3 * HH * BB;

    const int tid = threadIdx.x;
    const int ks  = tid >> 5;          // warp = k-slice 0..15
    const int rg  = (tid >> 4) & 1;    // gate-pair
    const int bq  = tid & 15;          // batch pair
    const int swz = bq & 7;
    const int b0  = 2 * bq;
    const int u4  = blockIdx.x * 4;

    // weight row bases (all matrices K=512)
    const int g0r = (2 * rg) * HH + u4;
    const int g1r = (2 * rg + 1) * HH + u4;
    const float* a_w0 = whh1 + g0r * 512 + ks * 32;
    const float* a_w1 = whh1 + g1r * 512 + ks * 32;
    const float* wBm  = (ks < 8) ? wih2 : whh2;
    const float* wCm  = (ks < 8) ? wih3 : whh3;
    const int koff = (ks & 7) * 64;
    const float* b_w0 = wBm + g0r * 512 + koff;
    const float* b_w1 = wBm + g1r * 512 + koff;
    const float* c_w0 = wCm + g0r * 512 + koff;
    const float* c_w1 = wCm + g1r * 512 + koff;

    // h smem slice bases (row b0; row b0+1 at +512)
    const float* hA = buf1 + b0 * 512 + ks * 32;
    const float* hB = ((ks < 8) ? buf1 : buf2) + b0 * 512 + koff;
    const float* hC = ((ks < 8) ? buf2 : buf3) + b0 * 512 + koff;

    // cell mapping (tid < 128)
    const int cu = tid >> 5;
    const int cb = tid & 31;
    const int cunit = u4 + cu;
    float c1 = 0.f, c2 = 0.f, c3 = 0.f, h3sum = 0.f;
    float bias2[4], bias3[4];
    if (tid < 128) {
#pragma unroll
        for (int g = 0; g < 4; ++g) {
            bias2[g] = b2[g * HH + cunit];
            bias3[g] = b3[g * HH + cunit];
        }
    }

    // staging: thread copies granule k4c for 8 b-rows
    const int k4c  = tid & 127;
    const int bseg = tid >> 7;      // 0..3
    const unsigned sb1 = (unsigned)__cvta_generic_to_shared(buf1);
    const unsigned sb2 = (unsigned)__cvta_generic_to_shared(buf2);
    const unsigned sb3 = (unsigned)__cvta_generic_to_shared(buf3);

    ull acc[8][2];

    for (int slot = 0; slot < NSLOT; ++slot) {
        const int rdp = (slot + 1) & 1;
        const int wrp = slot & 1;
        const bool v1 = slot < TT;
        const bool v2 = (slot >= 1) && (slot < TT + 1);
        const bool v3 = slot >= 2;

        // ---- async stage h1/h2/h3 (one commit group per buffer) ----
        {
            const char* s1 = (const char*)(g_hb1[rdp]);
            const char* s2 = (const char*)(g_hb2[rdp]);
            const char* s3 = (const char*)(g_hb3[rdp]);
#pragma unroll
            for (int j = 0; j < 8; ++j) {
                int b = bseg * 8 + j;
                unsigned doff = (unsigned)((b * 128 + (k4c ^ ((b >> 1) & 7))) * 16);
                unsigned soff = (unsigned)((b * 128 + k4c) * 16);
                CP_ASYNC16(sb1 + doff, s1 + soff);
            }
            CP_COMMIT();
#pragma unroll
            for (int j = 0; j < 8; ++j) {
                int b = bseg * 8 + j;
                unsigned doff = (unsigned)((b * 128 + (k4c ^ ((b >> 1) & 7))) * 16);
                unsigned soff = (unsigned)((b * 128 + k4c) * 16);
                CP_ASYNC16(sb2 + doff, s2 + soff);
            }
            CP_COMMIT();
#pragma unroll
            for (int j = 0; j < 8; ++j) {
                int b = bseg * 8 + j;
                unsigned doff = (unsigned)((b * 128 + (k4c ^ ((b >> 1) & 7))) * 16);
                unsigned soff = (unsigned)((b * 128 + k4c) * 16);
                CP_ASYNC16(sb3 + doff, s3 + soff);
            }
            CP_COMMIT();
        }
        float xg0 = 0.f, xg1 = 0.f, xg2 = 0.f, xg3 = 0.f;
        if (v1 && tid < 128) {
            const float* xb = xp + (cb * TT + slot) * G4 + cunit;
            xg0 = __ldg(xb);
            xg1 = __ldg(xb + HH);
            xg2 = __ldg(xb + 2 * HH);
            xg3 = __ldg(xb + 3 * HH);
        }

        // ---- phase A : layer 1 ----
        CP_WAIT(2);
        __syncthreads();
        if (v1) {
            gphase(acc, a_w0, a_w1, hA, hA + 512, swz, 8);
            store_part(part, acc, ks, rg, bq);
        }
        __syncthreads();
        if (v1 && tid < 128) {
            float4 g = cell_sum(part, cu, cb);
            g.x += xg0; g.y += xg1; g.z += xg2; g.w += xg3;
            float hv = lstm_cell(g, c1);
            __stcg(&g_hb1[wrp][cb * HH + cunit], hv);
        }
        CP_WAIT(1);
        __syncthreads();

        // ---- phase B : layer 2 ----
        if (v2) {
            gphase(acc, b_w0, b_w1, hB, hB + 512, swz, 16);
            store_part(part, acc, ks, rg, bq);
        }
        __syncthreads();
        if (v2 && tid < 128) {
            float4 g = cell_sum(part, cu, cb);
            g.x += bias2[0]; g.y += bias2[1]; g.z += bias2[2]; g.w += bias2[3];
            float hv = lstm_cell(g, c2);
            __stcg(&g_hb2[wrp][cb * HH + cunit], hv);
        }
        CP_WAIT(0);
        __syncthreads();

        // ---- phase C : layer 3 ----
        if (v3) {
            gphase(acc, c_w0, c_w1, hC, hC + 512, swz, 16);
            store_part(part, acc, ks, rg, bq);
        }
        __syncthreads();
        if (v3 && tid < 128) {
            float4 g = cell_sum(part, cu, cb);
            g.x += bias3[0]; g.y += bias3[1]; g.z += bias3[2]; g.w += bias3[3];
            float hv = lstm_cell(g, c3);
            __stcg(&g_hb3[wrp][cb * HH + cunit], hv);
            h3sum += hv;
        }

        grid_bar();
    }
    if (tid < 128)
        g_feat[cb * HH + cunit] = h3sum * (1.f / 512.f);
}

// --------------------------------- head ------------------------------------
__global__ __launch_bounds__(64) void head_kernel(
    const float* __restrict__ hw, const float* __restrict__ hb,
    float* __restrict__ outp)
{
    const int c = blockIdx.x, b = blockIdx.y;
    float s = 0.f;
    for (int k = threadIdx.x; k < HH; k += 64)
        s += g_feat[b * HH + k] * hw[c * HH + k];
    __shared__ float red[2];
#pragma unroll
    for (int o = 16; o; o >>= 1) s += __shfl_down_sync(0xffffffffu, s, o);
    if ((threadIdx.x & 31) == 0) red[threadIdx.x >> 5] = s;
    __syncthreads();
    if (threadIdx.x == 0) outp[b * NCLS + c] = red[0] + red[1] + hb[c];
}

// ------------------------------ launcher -----------------------------------
extern "C" void kernel_launch(void* const* d_in, const int* in_sizes, int n_in,
                              void* d_out, int out_size)
{
    const float* x_emg  = (const float*)d_in[0];
    const float* conv_w = (const float*)d_in[1];
    const float* gamma  = (const float*)d_in[2];
    const float* beta   = (const float*)d_in[3];
    const float *w_ih[3], *w_hh[3], *bi[3], *head_w, *head_b;

    if (in_sizes[4] == 4 * HH * FF) {          // signature order
        for (int l = 0; l < 3; ++l) {
            w_ih[l] = (const float*)d_in[4 + 3 * l];
            w_hh[l] = (const float*)d_in[5 + 3 * l];
            bi[l]   = (const float*)d_in[6 + 3 * l];
        }
        head_w = (const float*)d_in[13];
        head_b = (const float*)d_in[14];
    } else {                                    // dict order
        head_w = (const float*)d_in[4];
        head_b = (const float*)d_in[5];
        for (int l = 0; l < 3; ++l) {
            w_ih[l] = (const float*)d_in[6 + 3 * l];
            w_hh[l] = (const float*)d_in[7 + 3 * l];
            bi[l]   = (const float*)d_in[8 + 3 * l];
        }
    }
    float* out = (float*)d_out;

    cudaFuncSetAttribute(conv_kernel,
        cudaFuncAttributeMaxDynamicSharedMemorySize, CONV_SMEM);
    cudaFuncSetAttribute(fused_rec_kernel,
        cudaFuncAttributeMaxDynamicSharedMemorySize, FSMEM);

    float* g_xp_p;   cudaGetSymbolAddress((void**)&g_xp_p, g_xp);
    float* g_xt_p;   cudaGetSymbolAddress((void**)&g_xt_p, g_xt);

    conv_kernel<<<dim3(TT / 128, BB), 256, CONV_SMEM>>>(x_emg, conv_w);
    gn_stats_kernel<<<BB * GG, 256>>>();
    gn_apply_kernel<<<dim3(TT / 32, FF / 32, BB), 256>>>(gamma, beta);

    gemm_kernel<<<dim3(G4 / 64, BB * TT / 64), 256>>>(
        g_xt_p, w_ih[0], bi[0], g_xp_p, FF);

    zero_h_kernel<<<128, 256>>>();
    fused_rec_kernel<<<RNB, 512, FSMEM>>>(
        g_xp_p, w_hh[0], w_ih[1], w_hh[1], bi[1], w_ih[2], w_hh[2], bi[2]);

    head_kernel<<<dim3(NCLS, BB), 64>>>(head_w, head_b, out);
}